// round 7
// baseline (speedup 1.0000x reference)
#include <cuda_runtime.h>
#include <cuda_bf16.h>

#define WS 7
#define DROP_PROB 0.1f
#define Hc 250          // H - WS + 1
#define Wc 250
#define Hdim 256
#define Wdim 256
#define MASK_ELEMS (Hdim * Wdim)        // 65536
#define MASK_VEC4  (MASK_ELEMS / 4)     // 16384 (power of two)
#define TOTAL_VEC4 (16u * 64u * MASK_VEC4)   // 16777216
#define QUART_VEC4 (TOTAL_VEC4 / 4u)         // 4194304 = 256 * MASK_VEC4

// Scratch for the [256,256] broadcast mask (device global: no allocs allowed).
__device__ float g_mask[MASK_ELEMS];

// Kernel 1 (separable dilation): one block per output row h (256 blocks, 256 thr).
__global__ void build_mask_kernel(const float* __restrict__ u) {
    __shared__ int colOR[Wdim];
    int h = blockIdx.x;
    int w = threadIdx.x;

    int v = 0;
    if (w < Wc) {
        int a0 = h - (WS - 1); if (a0 < 0) a0 = 0;
        int a1 = h;            if (a1 > Hc - 1) a1 = Hc - 1;
        #pragma unroll 7
        for (int a = a0; a <= a1; ++a)
            v |= (__ldg(u + a * Wc + w) < DROP_PROB);
    }
    colOR[w] = v;
    __syncthreads();

    int b0 = w - (WS - 1); if (b0 < 0) b0 = 0;
    int b1 = w;            if (b1 > Wc - 1) b1 = Wc - 1;
    int d = 0;
    #pragma unroll 7
    for (int b = b0; b <= b1; ++b)
        d |= colOR[b];

    g_mask[h * Wdim + w] = d ? 0.0f : 1.0f;
}

// Kernel 2: write-bound streaming apply, 4 float4 per thread at quarter-tensor
// stride. QUART_VEC4 is a multiple of MASK_VEC4, so all four positions share
// the same (h,w) mask value -> ONE mask load amortized over 4 stores.
// ~99.4% of mask positions are 0: skip all x loads and write zeros.
__global__ void __launch_bounds__(256, 8)
apply_mask_kernel(const float4* __restrict__ x, float4* __restrict__ out) {
    unsigned int i = blockIdx.x * 256u + threadIdx.x;
    const float4* m4 = reinterpret_cast<const float4*>(g_mask);
    float4 mv = __ldg(m4 + (i & (MASK_VEC4 - 1)));

    float4 o0 = make_float4(0.f, 0.f, 0.f, 0.f);
    float4 o1 = o0, o2 = o0, o3 = o0;

    if ((mv.x + mv.y + mv.z + mv.w) != 0.0f) {
        float4 x0 = x[i];
        float4 x1 = x[i +     QUART_VEC4];
        float4 x2 = x[i + 2u * QUART_VEC4];
        float4 x3 = x[i + 3u * QUART_VEC4];
        o0.x = x0.x * mv.x; o0.y = x0.y * mv.y; o0.z = x0.z * mv.z; o0.w = x0.w * mv.w;
        o1.x = x1.x * mv.x; o1.y = x1.y * mv.y; o1.z = x1.z * mv.z; o1.w = x1.w * mv.w;
        o2.x = x2.x * mv.x; o2.y = x2.y * mv.y; o2.z = x2.z * mv.z; o2.w = x2.w * mv.w;
        o3.x = x3.x * mv.x; o3.y = x3.y * mv.y; o3.z = x3.z * mv.z; o3.w = x3.w * mv.w;
    }

    __stcs(out + i,                  o0);
    __stcs(out + i +     QUART_VEC4, o1);
    __stcs(out + i + 2u * QUART_VEC4, o2);
    __stcs(out + i + 3u * QUART_VEC4, o3);
}

extern "C" void kernel_launch(void* const* d_in, const int* in_sizes, int n_in,
                              void* d_out, int out_size) {
    const float* x = (const float*)d_in[0];   // [16,64,256,256] fp32
    const float* u = (const float*)d_in[1];   // [250,250] fp32
    float* out = (float*)d_out;

    // 1) build 256x256 mask (separable 7x7 max-dilation)
    build_mask_kernel<<<Hdim, Wdim>>>(u);

    // 2) apply: 16777216 float4 total, 4 per thread -> 4194304 threads
    apply_mask_kernel<<<QUART_VEC4 / 256, 256>>>(
        reinterpret_cast<const float4*>(x),
        reinterpret_cast<float4*>(out));
}

// round 8
// speedup vs baseline: 1.0565x; 1.0565x over previous
#include <cuda_runtime.h>
#include <cuda_bf16.h>

#define WS 7
#define DROP_PROB 0.1f
#define Hc 250          // H - WS + 1
#define Wc 250
#define Hdim 256
#define Wdim 256
#define HW_VEC4 (Hdim * Wdim / 4)       // 16384 float4 per (b,c) plane
#define ROW_VEC4 (Wdim / 4)             // 64 float4 per row
#define BC_TOTAL 1024                   // 16 * 64
#define BC_PER_BLOCK 16
#define BC_GROUPS (BC_TOTAL / BC_PER_BLOCK)   // 64

// Single fused kernel: each block = (one image row h) x (group of 16 bc planes).
// Prologue: recompute this row's 256-wide dilated mask from u (L2-resident,
// 7 coalesced loads/thread + separable OR in smem). Mainloop: 4 guarded float4
// stream-stores per thread. ~99.4% of mask is 0 -> x loads skipped, write-bound.
__global__ void __launch_bounds__(256, 8)
fused_dropout_kernel(const float4* __restrict__ x, float4* __restrict__ out,
                     const float* __restrict__ u) {
    __shared__ int colOR[Wdim];
    __shared__ __align__(16) float maskf[Wdim];

    int h   = blockIdx.x & 255;      // image row
    int bcg = blockIdx.x >> 8;       // bc-group 0..63
    int tid = threadIdx.x;

    // --- mask row prologue (separable 7x7 max-dilation, row h only) ---
    int v = 0;
    if (tid < Wc) {
        int a0 = h - (WS - 1); if (a0 < 0) a0 = 0;
        int a1 = h;            if (a1 > Hc - 1) a1 = Hc - 1;
        #pragma unroll 7
        for (int a = a0; a <= a1; ++a)
            v |= (__ldg(u + a * Wc + tid) < DROP_PROB);
    }
    colOR[tid] = v;
    __syncthreads();

    int b0 = tid - (WS - 1); if (b0 < 0) b0 = 0;
    int b1 = tid;            if (b1 > Wc - 1) b1 = Wc - 1;
    int d = 0;
    #pragma unroll 7
    for (int b = b0; b <= b1; ++b)
        d |= colOR[b];
    maskf[tid] = d ? 0.0f : 1.0f;
    __syncthreads();

    // --- streaming apply: 4 float4 per thread across 4 bc planes ---
    int w4  = tid & 63;              // float4 column within the row
    int bcl = tid >> 6;              // 0..3
    float4 mv = reinterpret_cast<const float4*>(maskf)[w4];

    int bc0 = bcg * BC_PER_BLOCK + bcl;            // bc planes: bc0 + {0,4,8,12}
    unsigned int base = (unsigned int)bc0 * HW_VEC4 + (unsigned int)h * ROW_VEC4 + w4;
    const unsigned int stride = 4u * HW_VEC4;      // 4 planes apart

    float4 o0 = make_float4(0.f, 0.f, 0.f, 0.f);
    float4 o1 = o0, o2 = o0, o3 = o0;

    if ((mv.x + mv.y + mv.z + mv.w) != 0.0f) {
        float4 x0 = x[base];
        float4 x1 = x[base + stride];
        float4 x2 = x[base + 2u * stride];
        float4 x3 = x[base + 3u * stride];
        o0.x = x0.x * mv.x; o0.y = x0.y * mv.y; o0.z = x0.z * mv.z; o0.w = x0.w * mv.w;
        o1.x = x1.x * mv.x; o1.y = x1.y * mv.y; o1.z = x1.z * mv.z; o1.w = x1.w * mv.w;
        o2.x = x2.x * mv.x; o2.y = x2.y * mv.y; o2.z = x2.z * mv.z; o2.w = x2.w * mv.w;
        o3.x = x3.x * mv.x; o3.y = x3.y * mv.y; o3.z = x3.z * mv.z; o3.w = x3.w * mv.w;
    }

    __stcs(out + base,               o0);
    __stcs(out + base + stride,      o1);
    __stcs(out + base + 2u * stride, o2);
    __stcs(out + base + 3u * stride, o3);
}

extern "C" void kernel_launch(void* const* d_in, const int* in_sizes, int n_in,
                              void* d_out, int out_size) {
    const float* x = (const float*)d_in[0];   // [16,64,256,256] fp32
    const float* u = (const float*)d_in[1];   // [250,250] fp32
    float* out = (float*)d_out;

    // 256 rows x 64 bc-groups = 16384 blocks, 256 threads, 4 float4/thread
    fused_dropout_kernel<<<Hdim * BC_GROUPS, 256>>>(
        reinterpret_cast<const float4*>(x),
        reinterpret_cast<float4*>(out),
        u);
}